// round 16
// baseline (speedup 1.0000x reference)
#include <cuda_runtime.h>
#include <cuda_bf16.h>
#include <cstdint>

#define GRID_N 64
#define NSAMP 128
#define HDIM 64
#define NRAY_MAX 8192
#define NSAMP_TOT (NRAY_MAX * NSAMP)

#define AMINX (-1.25f)
#define AMINY (-1.55f)
#define AMINZ (-1.25f)
#define SCALE (2.5f)

// ---- scratch (device globals) ----
__device__ float4   g_list[NSAMP_TOT];
__device__ float4   g_rgbsig[NSAMP_TOT];
__device__ unsigned g_maskbits[NRAY_MAX * 4];
__device__ int      g_count;

#define BF16X2(r, hi, lo) \
    asm("cvt.rn.bf16x2.f32 %0, %1, %2;" : "=r"(r) : "f"(hi), "f"(lo))

__device__ __forceinline__ void mma16816(float* d, const uint32_t* a,
                                         uint32_t b0, uint32_t b1) {
    asm volatile(
        "mma.sync.aligned.m16n8k16.row.col.f32.bf16.bf16.f32 "
        "{%0,%1,%2,%3}, {%4,%5,%6,%7}, {%8,%9}, {%0,%1,%2,%3};"
        : "+f"(d[0]), "+f"(d[1]), "+f"(d[2]), "+f"(d[3])
        : "r"(a[0]), "r"(a[1]), "r"(a[2]), "r"(a[3]), "r"(b0), "r"(b1));
}

// ============================================================
// K1: sampling + occupancy mask + global compaction (bit-exact)
// ============================================================
__global__ __launch_bounds__(512) void k1_sample(
    const float* __restrict__ rays_o, const float* __restrict__ rays_d,
    const float* __restrict__ near_, const float* __restrict__ far_,
    const float* __restrict__ jitter, const float* __restrict__ density,
    int N)
{
    __shared__ int warpcnt[16];
    __shared__ int base_s;

    const int tid  = threadIdx.x;
    const int w    = tid >> 5;
    const int lane = tid & 31;
    const int r    = tid >> 7;
    const int s    = tid & 127;
    const int n    = blockIdx.x * 4 + r;
    const bool valid = (n < N);

    bool mask = false;
    float px = 0.f, py = 0.f, pz = 0.f;

    if (valid) {
        const float jit = __ldg(&jitter[n * NSAMP + s]);
        const float ox = rays_o[3 * n + 0], oy = rays_o[3 * n + 1], oz = rays_o[3 * n + 2];
        const float dx = rays_d[3 * n + 0], dy = rays_d[3 * n + 1], dz = rays_d[3 * n + 2];
        const float nr = near_[n], fr = far_[n];
        const float step = __fmul_rn(__fsub_rn(fr, nr), 0.0078125f);

        const float z = __fadd_rn(nr, __fmul_rn((float)s, step));
        const float p0x = __fadd_rn(ox, __fmul_rn(z, dx));
        const float p0y = __fadd_rn(oy, __fmul_rn(z, dy));
        const float p0z = __fadd_rn(oz, __fmul_rn(z, dz));
        const float ux = __fmul_rn(__fdiv_rn(__fsub_rn(p0x, AMINX), SCALE), (float)GRID_N);
        const float uy = __fmul_rn(__fdiv_rn(__fsub_rn(p0y, AMINY), SCALE), (float)GRID_N);
        const float uz = __fmul_rn(__fdiv_rn(__fsub_rn(p0z, AMINZ), SCALE), (float)GRID_N);
        const int ix = (int)floorf(ux);
        const int iy = (int)floorf(uy);
        const int iz = (int)floorf(uz);
        const bool inb = (ix >= 0) & (ix < GRID_N) & (iy >= 0) & (iy < GRID_N)
                       & (iz >= 0) & (iz < GRID_N);
        const int cx = min(max(ix, 0), GRID_N - 1);
        const int cy = min(max(iy, 0), GRID_N - 1);
        const int cz = min(max(iz, 0), GRID_N - 1);
        const float dv = __ldg(&density[(cx << 12) + (cy << 6) + cz]);

        const float js  = __fmul_rn(jit, step);
        const float zvA = __fadd_rn(z, js);
        const float zvB = js;

        mask = inb && (dv > 0.5f);
        const float zv = mask ? zvA : zvB;
        px = __fadd_rn(ox, __fmul_rn(zv, dx));
        py = __fadd_rn(oy, __fmul_rn(zv, dy));
        pz = __fadd_rn(oz, __fmul_rn(zv, dz));
    }

    unsigned bal = __ballot_sync(0xffffffffu, mask);
    int pre = __popc(bal & ((1u << lane) - 1u));
    if (lane == 0) {
        warpcnt[w] = __popc(bal);
        if (valid) g_maskbits[n * 4 + (w & 3)] = bal;
    }
    __syncthreads();
    if (tid == 0) {
        int total = 0;
        #pragma unroll
        for (int i = 0; i < 16; i++) total += warpcnt[i];
        base_s = atomicAdd(&g_count, total);
    }
    int wbase = 0;
    #pragma unroll
    for (int i = 0; i < 16; i++) if (i < w) wbase += warpcnt[i];
    __syncthreads();

    if (mask) {
        int pos = base_s + wbase + pre;
        g_list[pos] = make_float4(px, py, pz, __int_as_float(n * NSAMP + s));
    }
}

// ============================================================
// K2: layer-2 GEMM via mma.sync m16n8k16 bf16 (hi/lo split, f32 acc)
//   Occupancy restructure: CTA = 128 threads (4 warps), tile = 128
//   samples, smem 54.3KB -> 4 CTAs/SM (4 independent barrier domains).
//   Each warp: 32 rows x 64 cols = 2m x 8n x 4k x 3 passes.
// ============================================================
#define A_STRIDE 144
#define B_STRIDE 136
#define OFF_AHI 0
#define OFF_ALO (128 * A_STRIDE)
#define OFF_BHI (2 * 128 * A_STRIDE)
#define OFF_BLO (2 * 128 * A_STRIDE + 64 * B_STRIDE)
#define DYN_SMEM (2 * 128 * A_STRIDE + 2 * 64 * B_STRIDE)   // 54272

__global__ __launch_bounds__(128, 4) void k2_mlp(
    const float* __restrict__ W1, const float* __restrict__ b1,
    const float* __restrict__ W2, const float* __restrict__ b2,
    const float* __restrict__ Wsig, const float* __restrict__ bsig,
    const float* __restrict__ Wrgb, const float* __restrict__ brgb)
{
    extern __shared__ __align__(16) char dyn[];
    char* const Ahi = dyn + OFF_AHI;
    char* const Alo = dyn + OFF_ALO;
    char* const Bhi = dyn + OFF_BHI;
    char* const Blo = dyn + OFF_BLO;

    __shared__ float  W1s[3 * HDIM];
    __shared__ float  b1s[HDIM];
    __shared__ __align__(8) float b2s[HDIM];
    __shared__ float4 Wos[HDIM];
    __shared__ float  bias4[4];
    __shared__ int    ids_s[128];

    const int tid  = threadIdx.x;
    const int w    = tid >> 5;
    const int lane = tid & 31;
    const int g    = lane >> 2;
    const int tg   = lane & 3;

    for (int i = tid; i < 3 * HDIM; i += 128) W1s[i] = W1[i];
    if (tid < HDIM) {
        b1s[tid] = b1[tid];
        b2s[tid] = b2[tid];
        Wos[tid] = make_float4(Wrgb[3 * tid + 0], Wrgb[3 * tid + 1],
                               Wrgb[3 * tid + 2], Wsig[tid]);
    }
    if (tid < 3) bias4[tid] = brgb[tid];
    if (tid == 3) bias4[3] = bsig[0];

    for (int idx = tid; idx < 64 * 32; idx += 128) {
        int nn = idx >> 5, kp = idx & 31;
        float w0 = W2[(2 * kp) * 64 + nn];
        float w1 = W2[(2 * kp + 1) * 64 + nn];
        uint32_t hp; BF16X2(hp, w1, w0);
        float hf0 = __uint_as_float(hp << 16);
        float hf1 = __uint_as_float(hp & 0xffff0000u);
        uint32_t lp; BF16X2(lp, w1 - hf1, w0 - hf0);
        *(uint32_t*)(Bhi + nn * B_STRIDE + kp * 4) = hp;
        *(uint32_t*)(Blo + nn * B_STRIDE + kp * 4) = lp;
    }
    __syncthreads();

    const int total  = g_count;
    const int ntiles = (total + 127) >> 7;

    for (int t = blockIdx.x; t < ntiles; t += gridDim.x) {
        // ---- layer 1: one sample per thread -> split bf16 hi/lo ----
        const int i = (t << 7) + tid;
        const bool live = (i < total);
        float px = 0.f, py = 0.f, pz = 0.f;
        int id = -1;
        if (live) {
            float4 e = g_list[i];
            px = e.x; py = e.y; pz = e.z;
            id = __float_as_int(e.w);
        }
        ids_s[tid] = id;
        {
            const uint32_t ro = (uint32_t)tid * A_STRIDE;
            uint4 hbuf, lbuf;
            uint32_t* hb = (uint32_t*)&hbuf;
            uint32_t* lb = (uint32_t*)&lbuf;
            #pragma unroll
            for (int k = 0; k < HDIM; k += 2) {
                float a0 = fmaf(px, W1s[k],     fmaf(py, W1s[HDIM + k],     fmaf(pz, W1s[2 * HDIM + k],     b1s[k])));
                float a1 = fmaf(px, W1s[k + 1], fmaf(py, W1s[HDIM + k + 1], fmaf(pz, W1s[2 * HDIM + k + 1], b1s[k + 1])));
                a0 = fmaxf(a0, 0.0f);
                a1 = fmaxf(a1, 0.0f);
                uint32_t hp; BF16X2(hp, a1, a0);
                float hf0 = __uint_as_float(hp << 16);
                float hf1 = __uint_as_float(hp & 0xffff0000u);
                uint32_t lp; BF16X2(lp, a1 - hf1, a0 - hf0);
                const int q = (k >> 1) & 3;
                hb[q] = hp;
                lb[q] = lp;
                if (q == 3) {   // flush 16B (k*2 - 12 is 16B-aligned: k%8==6 here)
                    *(uint4*)(Ahi + ro + k * 2 - 12) = hbuf;
                    *(uint4*)(Alo + ro + k * 2 - 12) = lbuf;
                }
            }
        }
        __syncthreads();

        // ---- MMA: 2 m-tiles x 8 n-tiles x 4 k-chunks x 3 passes ----
        float d[2][8][4];
        #pragma unroll
        for (int j = 0; j < 8; j++) {
            float2 bbj = *(const float2*)&b2s[8 * j + 2 * tg];
            d[0][j][0] = bbj.x; d[0][j][1] = bbj.y;
            d[0][j][2] = bbj.x; d[0][j][3] = bbj.y;
            d[1][j][0] = bbj.x; d[1][j][1] = bbj.y;
            d[1][j][2] = bbj.x; d[1][j][3] = bbj.y;
        }

        #pragma unroll
        for (int kc = 0; kc < 4; kc++) {
            const int kb = kc * 16;
            uint32_t ah[2][4], al[2][4];
            #pragma unroll
            for (int mt = 0; mt < 2; mt++) {
                const int rb = w * 32 + mt * 16 + g;
                const char* ph = Ahi + rb * A_STRIDE + (kb + 2 * tg) * 2;
                const char* pl = Alo + rb * A_STRIDE + (kb + 2 * tg) * 2;
                ah[mt][0] = *(const uint32_t*)(ph);
                ah[mt][1] = *(const uint32_t*)(ph + 8 * A_STRIDE);
                ah[mt][2] = *(const uint32_t*)(ph + 16);
                ah[mt][3] = *(const uint32_t*)(ph + 8 * A_STRIDE + 16);
                al[mt][0] = *(const uint32_t*)(pl);
                al[mt][1] = *(const uint32_t*)(pl + 8 * A_STRIDE);
                al[mt][2] = *(const uint32_t*)(pl + 16);
                al[mt][3] = *(const uint32_t*)(pl + 8 * A_STRIDE + 16);
            }
            #pragma unroll
            for (int j = 0; j < 8; j++) {
                const char* pb = Bhi + (8 * j + g) * B_STRIDE + (kb + 2 * tg) * 2;
                const char* ql = Blo + (8 * j + g) * B_STRIDE + (kb + 2 * tg) * 2;
                uint32_t bh0 = *(const uint32_t*)(pb);
                uint32_t bh1 = *(const uint32_t*)(pb + 16);
                uint32_t bl0 = *(const uint32_t*)(ql);
                uint32_t bl1 = *(const uint32_t*)(ql + 16);
                mma16816(d[0][j], ah[0], bh0, bh1);
                mma16816(d[1][j], ah[1], bh0, bh1);
                mma16816(d[0][j], al[0], bh0, bh1);
                mma16816(d[1][j], al[1], bh0, bh1);
                mma16816(d[0][j], ah[0], bl0, bl1);
                mma16816(d[1][j], ah[1], bl0, bl1);
            }
        }

        // ---- epilogue: relu + head dot products, reduce over tg ----
        float pr[4][4];
        #pragma unroll
        for (int q = 0; q < 4; q++) {
            pr[q][0] = 0.f; pr[q][1] = 0.f; pr[q][2] = 0.f; pr[q][3] = 0.f;
        }
        #pragma unroll
        for (int mt = 0; mt < 2; mt++) {
            #pragma unroll
            for (int j = 0; j < 8; j++) {
                float4 wl = Wos[8 * j + 2 * tg];
                float4 wh = Wos[8 * j + 2 * tg + 1];
                float h0 = fmaxf(d[mt][j][0], 0.f);
                float h1 = fmaxf(d[mt][j][1], 0.f);
                float h2 = fmaxf(d[mt][j][2], 0.f);
                float h3 = fmaxf(d[mt][j][3], 0.f);
                pr[2 * mt][0] = fmaf(h0, wl.x, fmaf(h1, wh.x, pr[2 * mt][0]));
                pr[2 * mt][1] = fmaf(h0, wl.y, fmaf(h1, wh.y, pr[2 * mt][1]));
                pr[2 * mt][2] = fmaf(h0, wl.z, fmaf(h1, wh.z, pr[2 * mt][2]));
                pr[2 * mt][3] = fmaf(h0, wl.w, fmaf(h1, wh.w, pr[2 * mt][3]));
                pr[2 * mt + 1][0] = fmaf(h2, wl.x, fmaf(h3, wh.x, pr[2 * mt + 1][0]));
                pr[2 * mt + 1][1] = fmaf(h2, wl.y, fmaf(h3, wh.y, pr[2 * mt + 1][1]));
                pr[2 * mt + 1][2] = fmaf(h2, wl.z, fmaf(h3, wh.z, pr[2 * mt + 1][2]));
                pr[2 * mt + 1][3] = fmaf(h2, wl.w, fmaf(h3, wh.w, pr[2 * mt + 1][3]));
            }
        }
        #pragma unroll
        for (int q = 0; q < 4; q++) {
            #pragma unroll
            for (int v = 0; v < 4; v++) {
                float val = pr[q][v];
                val += __shfl_down_sync(0xffffffffu, val, 2, 4);
                val += __shfl_down_sync(0xffffffffu, val, 1, 4);
                pr[q][v] = val;
            }
        }
        if (tg == 0) {
            const int rows[4] = { w * 32 + g, w * 32 + g + 8,
                                  w * 32 + 16 + g, w * 32 + 24 + g };
            #pragma unroll
            for (int q = 0; q < 4; q++) {
                int id2 = ids_s[rows[q]];
                if (id2 >= 0) {
                    float4 outv;
                    outv.x = 1.0f / (1.0f + __expf(-(pr[q][0] + bias4[0])));
                    outv.y = 1.0f / (1.0f + __expf(-(pr[q][1] + bias4[1])));
                    outv.z = 1.0f / (1.0f + __expf(-(pr[q][2] + bias4[2])));
                    outv.w = pr[q][3] + bias4[3];
                    g_rgbsig[id2] = outv;
                }
            }
        }
        __syncthreads();
    }
}

// ============================================================
// K3: per-ray composite, 4 rays per CTA; resets g_count
// ============================================================
__global__ __launch_bounds__(512) void k3_composite(
    const float* __restrict__ near_, const float* __restrict__ far_,
    float* __restrict__ out, int N)
{
    __shared__ float wtot[4][4];
    __shared__ float red[4][12];

    const int tid  = threadIdx.x;
    const int r    = tid >> 7;
    const int rt   = tid & 127;
    const int lane = tid & 31;
    const int wr   = rt >> 5;
    const int n    = blockIdx.x * 4 + r;

    if (blockIdx.x == 0 && tid == 0) g_count = 0;

    const bool valid = (n < N);
    float f = 1.0f, alpha = 0.0f;
    float4 rs = make_float4(0.f, 0.f, 0.f, 0.f);
    bool mask = false;

    if (valid) {
        const float step = __fmul_rn(__fsub_rn(far_[n], near_[n]), 0.0078125f);
        const unsigned bal = g_maskbits[n * 4 + wr];
        mask = (bal >> lane) & 1u;
        rs = g_rgbsig[n * NSAMP + rt];
        if (mask) {
            float tau = fmaxf(rs.w, 0.0f) * step;
            alpha = 1.0f - __expf(-tau);
        }
        f = 1.0f - alpha + 1e-10f;
    }

    float scan = f;
    #pragma unroll
    for (int off = 1; off < 32; off <<= 1) {
        float v = __shfl_up_sync(0xffffffffu, scan, off);
        if (lane >= off) scan *= v;
    }
    if (lane == 31) wtot[r][wr] = scan;
    __syncthreads();
    float prefix = 1.0f;
    #pragma unroll
    for (int i = 0; i < 4; i++) if (i < wr) prefix *= wtot[r][i];

    float excl = __shfl_up_sync(0xffffffffu, scan, 1);
    if (lane == 0) excl = 1.0f;
    float Tprev = excl * prefix;
    float wgt = alpha * Tprev;

    float c0 = 0.f, c1 = 0.f, c2 = 0.f;
    if (mask) {
        c0 = wgt * rs.x;
        c1 = wgt * rs.y;
        c2 = wgt * rs.z;
    }
    #pragma unroll
    for (int off = 16; off > 0; off >>= 1) {
        c0 += __shfl_down_sync(0xffffffffu, c0, off);
        c1 += __shfl_down_sync(0xffffffffu, c1, off);
        c2 += __shfl_down_sync(0xffffffffu, c2, off);
    }
    if (lane == 0) {
        red[r][wr * 3 + 0] = c0;
        red[r][wr * 3 + 1] = c1;
        red[r][wr * 3 + 2] = c2;
    }
    __syncthreads();
    if (rt == 0 && valid) {
        float nohit = wtot[r][0] * wtot[r][1] * wtot[r][2] * wtot[r][3];
        out[n * 3 + 0] = red[r][0] + red[r][3] + red[r][6] + red[r][9]  + nohit;
        out[n * 3 + 1] = red[r][1] + red[r][4] + red[r][7] + red[r][10] + nohit;
        out[n * 3 + 2] = red[r][2] + red[r][5] + red[r][8] + red[r][11] + nohit;
    }
}

extern "C" void kernel_launch(void* const* d_in, const int* in_sizes, int n_in,
                              void* d_out, int out_size) {
    const float* rays_o  = (const float*)d_in[0];
    const float* rays_d  = (const float*)d_in[1];
    const float* near_   = (const float*)d_in[2];
    const float* far_    = (const float*)d_in[3];
    const float* jitter  = (const float*)d_in[4];
    const float* density = (const float*)d_in[5];
    const float* W1   = (const float*)d_in[6];
    const float* b1   = (const float*)d_in[7];
    const float* W2   = (const float*)d_in[8];
    const float* b2   = (const float*)d_in[9];
    const float* Wsig = (const float*)d_in[10];
    const float* bsig = (const float*)d_in[11];
    const float* Wrgb = (const float*)d_in[12];
    const float* brgb = (const float*)d_in[13];
    float* out = (float*)d_out;

    const int N = in_sizes[2];

    cudaFuncSetAttribute(k2_mlp, cudaFuncAttributeMaxDynamicSharedMemorySize, DYN_SMEM);

    k1_sample<<<(N + 3) / 4, 512>>>(rays_o, rays_d, near_, far_, jitter, density, N);
    k2_mlp<<<592, 128, DYN_SMEM>>>(W1, b1, W2, b2, Wsig, bsig, Wrgb, brgb);
    k3_composite<<<(N + 3) / 4, 512>>>(near_, far_, out, N);
}